// round 1
// baseline (speedup 1.0000x reference)
#include <cuda_runtime.h>

// Problem constants (fixed by the reference setup_inputs).
#define BB 4
#define LQ 4096
#define LK 4096
#define DD 128

// Scratch (allocation-free rule: __device__ globals).
__device__ float g_sk[BB * LK];           // raw key scores
__device__ float g_p[BB * LK];            // softmax probabilities per batch
__device__ float g_part[BB * 32 * DD];    // partial p·val sums (32 j-chunks)
__device__ float g_outrow[BB * DD];       // final out row per batch

// ---------------------------------------------------------------------------
// K1: sk[b,j] = dot(key[b,j,:], w_k). One warp per (b,j) row, float4 loads.
// ---------------------------------------------------------------------------
__global__ __launch_bounds__(256) void sk_kernel(const float* __restrict__ key,
                                                 const float* __restrict__ w_k) {
    int warp = (blockIdx.x * blockDim.x + threadIdx.x) >> 5;   // 0 .. B*LK-1
    int lane = threadIdx.x & 31;
    int b = warp >> 12;            // /LK
    int j = warp & (LK - 1);
    const float4* row = reinterpret_cast<const float4*>(key + ((size_t)b * LK + j) * DD);
    const float4* wk4 = reinterpret_cast<const float4*>(w_k);
    float4 kv = row[lane];         // 32 lanes x 16B = 128 floats, coalesced
    float4 wv = wk4[lane];         // 512B, L1-resident
    float acc = kv.x * wv.x + kv.y * wv.y + kv.z * wv.z + kv.w * wv.w;
    #pragma unroll
    for (int o = 16; o > 0; o >>= 1) acc += __shfl_xor_sync(0xFFFFFFFFu, acc, o);
    if (lane == 0) g_sk[warp] = acc;
}

// ---------------------------------------------------------------------------
// K2: per-batch softmax over sk (4096 values). One block per batch.
// ---------------------------------------------------------------------------
__global__ __launch_bounds__(1024) void softmax_kernel() {
    const int b = blockIdx.x;
    const int tid = threadIdx.x;
    __shared__ float s_red[32];

    float v[4];
    float mx = -1e30f;
    #pragma unroll
    for (int r = 0; r < 4; ++r) {
        v[r] = g_sk[b * LK + tid + r * 1024];
        mx = fmaxf(mx, v[r]);
    }
    // block max
    #pragma unroll
    for (int o = 16; o > 0; o >>= 1) mx = fmaxf(mx, __shfl_xor_sync(0xFFFFFFFFu, mx, o));
    if ((tid & 31) == 0) s_red[tid >> 5] = mx;
    __syncthreads();
    if (tid < 32) {
        float m = s_red[tid];
        #pragma unroll
        for (int o = 16; o > 0; o >>= 1) m = fmaxf(m, __shfl_xor_sync(0xFFFFFFFFu, m, o));
        if (tid == 0) s_red[0] = m;
    }
    __syncthreads();
    mx = s_red[0];
    __syncthreads();

    float sum = 0.f;
    #pragma unroll
    for (int r = 0; r < 4; ++r) {
        v[r] = expf(v[r] - mx);
        sum += v[r];
    }
    #pragma unroll
    for (int o = 16; o > 0; o >>= 1) sum += __shfl_xor_sync(0xFFFFFFFFu, sum, o);
    if ((tid & 31) == 0) s_red[tid >> 5] = sum;
    __syncthreads();
    if (tid < 32) {
        float s = s_red[tid];
        #pragma unroll
        for (int o = 16; o > 0; o >>= 1) s += __shfl_xor_sync(0xFFFFFFFFu, s, o);
        if (tid == 0) s_red[0] = s;
    }
    __syncthreads();
    const float inv = 1.0f / s_red[0];
    #pragma unroll
    for (int r = 0; r < 4; ++r)
        g_p[b * LK + tid + r * 1024] = v[r] * inv;
}

// ---------------------------------------------------------------------------
// K3: partial out_row: chunk c covers j in [c*128, c*128+128).
// grid = (32, B), 128 threads (one per d). Deterministic fixed-order sums.
// ---------------------------------------------------------------------------
__global__ __launch_bounds__(128) void outrow_partial_kernel(const float* __restrict__ val) {
    const int b = blockIdx.y;
    const int chunk = blockIdx.x;
    const int d = threadIdx.x;
    const float* vb = val + (size_t)b * LK * DD;
    const float* pb = g_p + b * LK;
    const int j0 = chunk * 128;
    float acc = 0.f;
    #pragma unroll 4
    for (int j = j0; j < j0 + 128; ++j)
        acc += pb[j] * vb[(size_t)j * DD + d];
    g_part[(b * 32 + chunk) * DD + d] = acc;
}

// K4: reduce the 32 chunks. B*D = 512 threads total.
__global__ void outrow_reduce_kernel() {
    int idx = blockIdx.x * blockDim.x + threadIdx.x;   // 0..511
    int base = (idx >> 7) * 32 * DD + (idx & (DD - 1));
    float s = 0.f;
    #pragma unroll
    for (int c = 0; c < 32; ++c) s += g_part[base + c * DD];
    g_outrow[idx] = s;
}

// ---------------------------------------------------------------------------
// K5: broadcast-write out[b,i,d] = out_row[b,d].  B*LQ*D/4 = 524288 float4.
// ---------------------------------------------------------------------------
__global__ __launch_bounds__(256) void write_out_kernel(float4* __restrict__ out4) {
    const float4* row4 = reinterpret_cast<const float4*>(g_outrow);
    const int n = BB * LQ * DD / 4;
    int stride = gridDim.x * blockDim.x;
    for (int t = blockIdx.x * blockDim.x + threadIdx.x; t < n; t += stride) {
        int b = t >> 17;           // LQ*D/4 = 131072
        int d4 = t & 31;           // D/4 = 32
        out4[t] = row4[b * 32 + d4];
    }
}

// ---------------------------------------------------------------------------
// K6: broadcast-write att[b,i,j] = p[b,j].  B*LQ*LK/4 = 16777216 float4.
// This is the HBM-store-bound kernel (~256 MB). p lives in L2 (64 KB).
// ---------------------------------------------------------------------------
__global__ __launch_bounds__(256) void write_att_kernel(float4* __restrict__ att4) {
    const float4* p4 = reinterpret_cast<const float4*>(g_p);
    const size_t n = (size_t)BB * LQ * LK / 4;
    const size_t stride = (size_t)gridDim.x * blockDim.x;
    for (size_t t = (size_t)blockIdx.x * blockDim.x + threadIdx.x; t < n; t += stride) {
        int b = (int)(t >> 22);    // LQ*LK/4 = 4194304
        int jv = (int)(t & 1023);  // LK/4 = 1024
        att4[t] = p4[(b << 10) + jv];
    }
}

// ---------------------------------------------------------------------------
// Inputs (metadata order): 0=qry, 1=key, 2=val, 3=w_q, 4=w_k.
// qry and w_q are mathematically irrelevant (softmax shift-invariance).
// Output: tuple (out, att) concatenated: out = B*LQ*D floats, then att.
// ---------------------------------------------------------------------------
extern "C" void kernel_launch(void* const* d_in, const int* in_sizes, int n_in,
                              void* d_out, int out_size) {
    const float* key = (const float*)d_in[1];
    const float* val = (const float*)d_in[2];
    const float* w_k = (const float*)d_in[4];
    float* out = (float*)d_out;
    float* att = out + (size_t)BB * LQ * DD;

    sk_kernel<<<BB * LK * 32 / 256, 256>>>(key, w_k);
    softmax_kernel<<<BB, 1024>>>();
    outrow_partial_kernel<<<dim3(32, BB), 128>>>(val);
    outrow_reduce_kernel<<<2, 256>>>();
    write_out_kernel<<<512, 256>>>(reinterpret_cast<float4*>(out));
    write_att_kernel<<<4736, 256>>>(reinterpret_cast<float4*>(att));
}

// round 2
// speedup vs baseline: 1.2434x; 1.2434x over previous
#include <cuda_runtime.h>

// Problem constants (fixed by the reference setup_inputs).
#define BB 4
#define LQ 4096
#define LK 4096
#define DD 128

#define NCHUNK 32                 // j-chunks per batch for the p·val pass
#define CHUNK_J (LK / NCHUNK)     // 128 j's per chunk

// Scratch (allocation-free rule: __device__ globals).
__device__ float g_sk[BB * LK];              // raw key scores
__device__ float g_p[BB * LK];               // softmax probabilities per batch
__device__ float g_part[BB * NCHUNK * DD];   // partial p·val sums

// ---------------------------------------------------------------------------
// K1: sk[b,j] = dot(key[b,j,:], w_k). One warp per (b,j) row, float4 loads.
// ---------------------------------------------------------------------------
__global__ __launch_bounds__(256) void sk_kernel(const float* __restrict__ key,
                                                 const float* __restrict__ w_k) {
    int warp = (blockIdx.x * blockDim.x + threadIdx.x) >> 5;   // 0 .. B*LK-1
    int lane = threadIdx.x & 31;
    const float4* row = reinterpret_cast<const float4*>(key + (size_t)warp * DD);
    const float4* wk4 = reinterpret_cast<const float4*>(w_k);
    float4 kv = row[lane];         // 32 lanes x 16B = 128 floats, coalesced
    float4 wv = wk4[lane];         // 512B, L1-resident
    float acc = kv.x * wv.x + kv.y * wv.y + kv.z * wv.z + kv.w * wv.w;
    #pragma unroll
    for (int o = 16; o > 0; o >>= 1) acc += __shfl_xor_sync(0xFFFFFFFFu, acc, o);
    if (lane == 0) g_sk[warp] = acc;
}

// ---------------------------------------------------------------------------
// K2: fused softmax + p·val chunk partial.
// grid = (NCHUNK, BB), 256 threads. Every block redundantly (and
// deterministically identically) computes the batch softmax stats from g_sk,
// then writes p for its own 128-j chunk and the partial outrow over that chunk.
// ---------------------------------------------------------------------------
__global__ __launch_bounds__(256) void p_partial_kernel(const float* __restrict__ val) {
    const int b = blockIdx.y;
    const int chunk = blockIdx.x;
    const int tid = threadIdx.x;

    __shared__ float s_red[8];
    __shared__ float s_stat[2];          // [0]=max, [1]=inv_sum
    __shared__ float s_p[CHUNK_J];       // p for this chunk
    __shared__ float s_acc[256];

    // --- batch softmax stats (identical in every block of this batch) ---
    float v[16];
    float mx = -1e30f;
    #pragma unroll
    for (int r = 0; r < 16; ++r) {
        v[r] = g_sk[b * LK + tid + r * 256];
        mx = fmaxf(mx, v[r]);
    }
    #pragma unroll
    for (int o = 16; o > 0; o >>= 1) mx = fmaxf(mx, __shfl_xor_sync(0xFFFFFFFFu, mx, o));
    if ((tid & 31) == 0) s_red[tid >> 5] = mx;
    __syncthreads();
    if (tid < 8) {
        float m = s_red[tid];
        #pragma unroll
        for (int o = 4; o > 0; o >>= 1) m = fmaxf(m, __shfl_xor_sync(0xFFu, m, o));
        if (tid == 0) s_stat[0] = m;
    }
    __syncthreads();
    mx = s_stat[0];

    float sum = 0.f;
    #pragma unroll
    for (int r = 0; r < 16; ++r) sum += expf(v[r] - mx);
    #pragma unroll
    for (int o = 16; o > 0; o >>= 1) sum += __shfl_xor_sync(0xFFFFFFFFu, sum, o);
    __syncthreads();
    if ((tid & 31) == 0) s_red[tid >> 5] = sum;
    __syncthreads();
    if (tid < 8) {
        float s = s_red[tid];
        #pragma unroll
        for (int o = 4; o > 0; o >>= 1) s += __shfl_xor_sync(0xFFu, s, o);
        if (tid == 0) s_stat[1] = 1.0f / s;
    }
    __syncthreads();
    const float inv = s_stat[1];

    // --- p for this chunk ---
    const int j0 = chunk * CHUNK_J;
    if (tid < CHUNK_J) {
        float p = expf(g_sk[b * LK + j0 + tid] - mx) * inv;
        s_p[tid] = p;
        g_p[b * LK + j0 + tid] = p;
    }
    __syncthreads();

    // --- partial outrow over this chunk: thread (d = tid&127, half = tid>>7) ---
    const int d = tid & (DD - 1);
    const int half = tid >> 7;
    const float* vbase = val + (((size_t)b * LK + j0 + half * 64) * DD) + d;
    float acc = 0.f;
    #pragma unroll 4
    for (int jj = 0; jj < 64; ++jj)
        acc += s_p[half * 64 + jj] * vbase[(size_t)jj * DD];
    s_acc[tid] = acc;
    __syncthreads();
    if (tid < DD)
        g_part[(b * NCHUNK + chunk) * DD + tid] = s_acc[tid] + s_acc[tid + DD];
}

// ---------------------------------------------------------------------------
// K3: mega-writer.
//   blocks [0, OUT_BLOCKS):       reduce partials (redundant, from L2) and
//                                 write out (8 MB).
//   blocks [OUT_BLOCKS, +ATT_B):  stream att (256 MB) — the long pole.
// ---------------------------------------------------------------------------
#define OUT_BLOCKS 512
#define ATT_BLOCKS 4736

__global__ __launch_bounds__(256) void mega_writer_kernel(float4* __restrict__ out4,
                                                          float4* __restrict__ att4) {
    const int tid = threadIdx.x;

    if (blockIdx.x < OUT_BLOCKS) {
        // ---- out writer: 1024 float4 per block; 128 blocks per batch ----
        const int bid = blockIdx.x;
        const int b = bid >> 7;                 // 128 blocks per batch
        __shared__ float s_row[DD];
        if (tid < DD) {
            float s = 0.f;
            #pragma unroll
            for (int c = 0; c < NCHUNK; ++c)
                s += g_part[(b * NCHUNK + c) * DD + tid];
            s_row[tid] = s;
        }
        __syncthreads();
        const float4* row4 = reinterpret_cast<const float4*>(s_row);
        size_t base = (size_t)bid * 1024;       // float4 index into out
        #pragma unroll
        for (int r = 0; r < 4; ++r) {
            size_t t = base + tid + r * 256;
            out4[t] = row4[t & 31];             // D/4 = 32
        }
    } else {
        // ---- att writer: grid-stride over 64M float4 ----
        const float4* p4 = reinterpret_cast<const float4*>(g_p);
        const size_t n = (size_t)BB * LQ * LK / 4;
        const size_t stride = (size_t)ATT_BLOCKS * 256;
        size_t t = (size_t)(blockIdx.x - OUT_BLOCKS) * 256 + tid;
        for (; t < n; t += stride) {
            int b = (int)(t >> 22);             // LQ*LK/4 = 4194304
            int jv = (int)(t & 1023);           // LK/4 = 1024
            att4[t] = p4[(b << 10) + jv];
        }
    }
}

// ---------------------------------------------------------------------------
// Inputs (metadata order): 0=qry, 1=key, 2=val, 3=w_q, 4=w_k.
// qry and w_q are mathematically irrelevant (softmax shift-invariance).
// Output: tuple (out, att) concatenated: out = B*LQ*D floats, then att.
// ---------------------------------------------------------------------------
extern "C" void kernel_launch(void* const* d_in, const int* in_sizes, int n_in,
                              void* d_out, int out_size) {
    const float* key = (const float*)d_in[1];
    const float* val = (const float*)d_in[2];
    const float* w_k = (const float*)d_in[4];
    float* out = (float*)d_out;
    float* att = out + (size_t)BB * LQ * DD;

    sk_kernel<<<BB * LK * 32 / 256, 256>>>(key, w_k);
    p_partial_kernel<<<dim3(NCHUNK, BB), 256>>>(val);
    mega_writer_kernel<<<OUT_BLOCKS + ATT_BLOCKS, 256>>>(
        reinterpret_cast<float4*>(out), reinterpret_cast<float4*>(att));
}

// round 4
// speedup vs baseline: 1.3793x; 1.1093x over previous
#include <cuda_runtime.h>

// Problem constants (fixed by the reference setup_inputs).
#define BB 4
#define LQ 4096
#define LK 4096
#define DD 128

#define NCHUNK 32                 // j-chunks per batch for the p·val pass
#define CHUNK_J (LK / NCHUNK)     // 128 j's per chunk

// Scratch (allocation-free rule: __device__ globals).
__device__ float g_sk[BB * LK];              // raw key scores
__device__ float g_p[BB * LK];               // softmax probabilities per batch
__device__ float g_part[BB * NCHUNK * DD];   // partial p·val sums

// ---------------------------------------------------------------------------
// K1: sk[b,j] = dot(key[b,j,:], w_k).
// 8 lanes per row, 4 float4 per lane -> 4 independent loads in flight.
// Block = 256 threads = 32 rows. Grid = 512.
// ---------------------------------------------------------------------------
__global__ __launch_bounds__(256) void sk_kernel(const float* __restrict__ key,
                                                 const float* __restrict__ w_k) {
    const int lane = threadIdx.x & 31;
    const int sub = lane & 7;                       // lane within 8-lane row group
    const int row = (blockIdx.x * 256 + threadIdx.x) >> 3;   // global (b*LK+j)
    const float4* r4 = reinterpret_cast<const float4*>(key + (size_t)row * DD);
    const float4* wk4 = reinterpret_cast<const float4*>(w_k);

    float4 kv0 = r4[sub +  0];
    float4 kv1 = r4[sub +  8];
    float4 kv2 = r4[sub + 16];
    float4 kv3 = r4[sub + 24];
    float4 w0 = wk4[sub +  0];
    float4 w1 = wk4[sub +  8];
    float4 w2 = wk4[sub + 16];
    float4 w3 = wk4[sub + 24];

    float acc = kv0.x * w0.x + kv0.y * w0.y + kv0.z * w0.z + kv0.w * w0.w;
    acc += kv1.x * w1.x + kv1.y * w1.y + kv1.z * w1.z + kv1.w * w1.w;
    acc += kv2.x * w2.x + kv2.y * w2.y + kv2.z * w2.z + kv2.w * w2.w;
    acc += kv3.x * w3.x + kv3.y * w3.y + kv3.z * w3.z + kv3.w * w3.w;

    acc += __shfl_xor_sync(0xFFFFFFFFu, acc, 4);
    acc += __shfl_xor_sync(0xFFFFFFFFu, acc, 2);
    acc += __shfl_xor_sync(0xFFFFFFFFu, acc, 1);
    if (sub == 0) g_sk[row] = acc;
}

// ---------------------------------------------------------------------------
// K2: fused softmax + p·val chunk partial.
// grid = (NCHUNK, BB), 256 threads. Every block redundantly (and
// deterministically identically) computes the batch softmax stats from g_sk,
// then writes p for its own 128-j chunk and the partial outrow over that chunk.
// ---------------------------------------------------------------------------
__global__ __launch_bounds__(256) void p_partial_kernel(const float* __restrict__ val) {
    const int b = blockIdx.y;
    const int chunk = blockIdx.x;
    const int tid = threadIdx.x;

    __shared__ float s_red[8];
    __shared__ float s_stat[2];          // [0]=max, [1]=inv_sum
    __shared__ float s_p[CHUNK_J];       // p for this chunk
    __shared__ float s_acc[256];

    // --- batch softmax stats (identical in every block of this batch) ---
    float v[16];
    float mx = -1e30f;
    #pragma unroll
    for (int r = 0; r < 16; ++r) {
        v[r] = g_sk[b * LK + tid + r * 256];
        mx = fmaxf(mx, v[r]);
    }
    #pragma unroll
    for (int o = 16; o > 0; o >>= 1) mx = fmaxf(mx, __shfl_xor_sync(0xFFFFFFFFu, mx, o));
    if ((tid & 31) == 0) s_red[tid >> 5] = mx;
    __syncthreads();
    if (tid < 8) {
        float m = s_red[tid];
        #pragma unroll
        for (int o = 4; o > 0; o >>= 1) m = fmaxf(m, __shfl_xor_sync(0xFFu, m, o));
        if (tid == 0) s_stat[0] = m;
    }
    __syncthreads();
    mx = s_stat[0];

    float sum = 0.f;
    #pragma unroll
    for (int r = 0; r < 16; ++r) sum += expf(v[r] - mx);
    #pragma unroll
    for (int o = 16; o > 0; o >>= 1) sum += __shfl_xor_sync(0xFFFFFFFFu, sum, o);
    __syncthreads();
    if ((tid & 31) == 0) s_red[tid >> 5] = sum;
    __syncthreads();
    if (tid < 8) {
        float s = s_red[tid];
        #pragma unroll
        for (int o = 4; o > 0; o >>= 1) s += __shfl_xor_sync(0xFFu, s, o);
        if (tid == 0) s_stat[1] = 1.0f / s;
    }
    __syncthreads();
    const float inv = s_stat[1];

    // --- p for this chunk ---
    const int j0 = chunk * CHUNK_J;
    if (tid < CHUNK_J) {
        float p = expf(g_sk[b * LK + j0 + tid] - mx) * inv;
        s_p[tid] = p;
        g_p[b * LK + j0 + tid] = p;
    }
    __syncthreads();

    // --- partial outrow over this chunk: thread (d = tid&127, half = tid>>7) ---
    const int d = tid & (DD - 1);
    const int half = tid >> 7;
    const float* vbase = val + (((size_t)b * LK + j0 + half * 64) * DD) + d;
    float acc = 0.f;
    #pragma unroll 4
    for (int jj = 0; jj < 64; ++jj)
        acc += s_p[half * 64 + jj] * vbase[(size_t)jj * DD];
    s_acc[tid] = acc;
    __syncthreads();
    if (tid < DD)
        g_part[(b * NCHUNK + chunk) * DD + tid] = s_acc[tid] + s_acc[tid + DD];
}

// ---------------------------------------------------------------------------
// K3: mega-writer.
//   blocks [0, ATT_BLOCKS):  att (256 MB) — the long pole, scheduled FIRST.
//       Each block owns 8 full rows of one batch; the 16 KB p row is staged
//       in shared once, then pure __stcs (evict-first) streaming stores.
//   blocks [ATT_BLOCKS, +OUT_BLOCKS): reduce partials (redundant, from L2)
//       and write out (8 MB) with streaming stores.
// ---------------------------------------------------------------------------
#define OUT_BLOCKS 512
#define ROWS_PER_BLK 8
#define ATT_BLOCKS (BB * LQ / ROWS_PER_BLK)   // 2048

__global__ __launch_bounds__(256) void mega_writer_kernel(float4* __restrict__ out4,
                                                          float4* __restrict__ att4) {
    const int tid = threadIdx.x;

    if (blockIdx.x < ATT_BLOCKS) {
        // ---- att writer ----
        const int bid = blockIdx.x;                    // 0 .. ATT_BLOCKS-1
        const int row0 = bid * ROWS_PER_BLK;           // global row (b*LQ + i)
        const int b = row0 >> 12;                      // / LQ

        __shared__ float4 s_p4[LK / 4];                // 16 KB: full p row
        const float4* p4 = reinterpret_cast<const float4*>(g_p) + (b << 10);
        #pragma unroll
        for (int r = 0; r < 4; ++r)
            s_p4[tid + r * 256] = p4[tid + r * 256];
        __syncthreads();

        float4* dst = att4 + (size_t)row0 * (LK / 4);
        #pragma unroll
        for (int rr = 0; rr < ROWS_PER_BLK; ++rr) {
            #pragma unroll
            for (int r = 0; r < 4; ++r) {
                int c = tid + r * 256;
                __stcs(dst + (size_t)rr * (LK / 4) + c, s_p4[c]);
            }
        }
    } else {
        // ---- out writer: 1024 float4 per block; 128 blocks per batch ----
        const int bid = blockIdx.x - ATT_BLOCKS;       // 0 .. OUT_BLOCKS-1
        const int b = bid >> 7;                        // 128 blocks per batch
        __shared__ float s_row[DD];
        if (tid < DD) {
            float s = 0.f;
            #pragma unroll
            for (int c = 0; c < NCHUNK; ++c)
                s += g_part[(b * NCHUNK + c) * DD + tid];
            s_row[tid] = s;
        }
        __syncthreads();
        const float4* row4 = reinterpret_cast<const float4*>(s_row);
        size_t base = (size_t)bid * 1024;              // float4 index into out
        #pragma unroll
        for (int r = 0; r < 4; ++r) {
            size_t t = base + tid + r * 256;
            __stcs(out4 + t, row4[t & 31]);            // D/4 = 32
        }
    }
}

// ---------------------------------------------------------------------------
// Inputs (metadata order): 0=qry, 1=key, 2=val, 3=w_q, 4=w_k.
// qry and w_q are mathematically irrelevant (softmax shift-invariance).
// Output: tuple (out, att) concatenated: out = B*LQ*D floats, then att.
// ---------------------------------------------------------------------------
extern "C" void kernel_launch(void* const* d_in, const int* in_sizes, int n_in,
                              void* d_out, int out_size) {
    const float* key = (const float*)d_in[1];
    const float* val = (const float*)d_in[2];
    const float* w_k = (const float*)d_in[4];
    float* out = (float*)d_out;
    float* att = out + (size_t)BB * LQ * DD;

    sk_kernel<<<BB * LK / 32, 256>>>(key, w_k);
    p_partial_kernel<<<dim3(NCHUNK, BB), 256>>>(val);
    mega_writer_kernel<<<ATT_BLOCKS + OUT_BLOCKS, 256>>>(
        reinterpret_cast<float4*>(out), reinterpret_cast<float4*>(att));
}